// round 14
// baseline (speedup 1.0000x reference)
#include <cuda_runtime.h>
#include <cuda_bf16.h>
#include <cstdint>

#define S_LEN  262144
#define NDIM   128
#define TILE   128
#define NTILES 2048
#define NCTA   148        // 1 CTA/SM, 512 threads (all co-resident)
#define NPROD  128        // producer CTAs for W

// ---------------- device scratch ----------------
__device__ __align__(16) __nv_bfloat16 g_Bsw[NDIM * NDIM];  // B[t][k]=bf16(M[k][t]), swizzled
__device__ float g_partials[NCTA];
__device__ float g_l1part[NPROD];
__device__ int   g_done;       // producer counter (reset by last CTA)
__device__ int   g_ticket;     // completion ticket (reset by last CTA)

// ---------------- smem byte offsets (per CTA 169984 B, 1 CTA/SM) ----------------
#define STG0  0          // fp32 staging buf0: 128 x 512B = 65536
#define STG1  65536      // buf1
#define BOF   131072     // B bf16 swizzled: 32768
#define NXT   163840     // boundary rows fp32: 2 slots x 512
#define RED   164864     // reduction: 512 doubles = 4096 (aliases producer l1 floats)
#define SMEM_BYTES 169984

// ---------------- helpers ----------------
__device__ __forceinline__ uint32_t smem_u32(const void* p) {
    uint32_t a;
    asm("{ .reg .u64 t; cvta.to.shared.u64 t, %1; cvt.u32.u64 %0, t; }" : "=r"(a) : "l"(p));
    return a;
}
__device__ __forceinline__ uint32_t bf2(float xh, float xl) {
    uint32_t r;
    asm("cvt.rn.bf16x2.f32 %0, %1, %2;" : "=r"(r) : "f"(xh), "f"(xl));
    return r;
}
__device__ __forceinline__ float4 lds128f(uint32_t a) {
    float4 v;
    asm volatile("ld.shared.v4.f32 {%0,%1,%2,%3}, [%4];"
                 : "=f"(v.x), "=f"(v.y), "=f"(v.z), "=f"(v.w) : "r"(a));
    return v;
}
__device__ __forceinline__ float2 lds64f(uint32_t a) {
    float2 v;
    asm volatile("ld.shared.v2.f32 {%0,%1}, [%2];" : "=f"(v.x), "=f"(v.y) : "r"(a));
    return v;
}
__device__ __forceinline__ uint2 lds64u(uint32_t a) {
    uint2 v;
    asm volatile("ld.shared.v2.b32 {%0,%1}, [%2];" : "=r"(v.x), "=r"(v.y) : "r"(a));
    return v;
}
__device__ __forceinline__ void cpa16(uint32_t dst, const void* src) {
    asm volatile("cp.async.cg.shared.global [%0], [%1], 16;" :: "r"(dst), "l"(src));
}
__device__ __forceinline__ void cpa_commit() { asm volatile("cp.async.commit_group;" ::: "memory"); }
__device__ __forceinline__ void cpa_wait0()  { asm volatile("cp.async.wait_group 0;" ::: "memory"); }
__device__ __forceinline__ void cpa_wait1()  { asm volatile("cp.async.wait_group 1;" ::: "memory"); }

__device__ __forceinline__ void mma_bf16(float* d, const uint32_t* a, uint32_t b0, uint32_t b1) {
    asm volatile(
        "mma.sync.aligned.m16n8k16.row.col.f32.bf16.bf16.f32 "
        "{%0,%1,%2,%3}, {%4,%5,%6,%7}, {%8,%9}, {%0,%1,%2,%3};"
        : "+f"(d[0]), "+f"(d[1]), "+f"(d[2]), "+f"(d[3])
        : "r"(a[0]), "r"(a[1]), "r"(a[2]), "r"(a[3]), "r"(b0), "r"(b1));
}
__device__ __forceinline__ float softplusf(float x) {
    const float l = __logf(1.0f + __expf(x));
    return (x > 15.0f) ? x : l;
}
// swizzled byte offset: B plane row t (256B rows), element index k
__device__ __forceinline__ uint32_t gsw(int t, int k) {
    return (uint32_t)(t * 256 + (((k >> 2) ^ ((t & 7) << 2)) << 3) + (k & 3) * 2);
}

// ---------------- fused persistent kernel ----------------
extern __shared__ char dsm[];

__device__ __forceinline__ void issue_prefetch(const float* __restrict__ In, int tile,
                                               uint32_t sb, int slot, int tid) {
    const char* src = (const char*)(In + (size_t)tile * TILE * NDIM);
    const uint32_t stg = sb + (slot ? STG1 : STG0);
#pragma unroll
    for (int j = 0; j < 8; ++j) {
        const int idx = tid + 512 * j;           // 4096 16B chunks
        const int r = idx >> 5, c = idx & 31;
        cpa16(stg + r * 512 + ((c ^ ((r & 1) << 2)) << 4), src + r * 512 + c * 16);
    }
    if (tid < 32) {
        size_t nr = (size_t)tile * TILE + TILE;   // boundary row
        if (nr >= S_LEN) nr = 0;                   // clamped; masked in epilogue
        cpa16(sb + NXT + slot * 512 + tid * 16, (const char*)(In + nr * NDIM) + tid * 16);
    }
    cpa_commit();
}

__global__ void __launch_bounds__(512, 1)
fused_kernel(const float* __restrict__ In, const float* __restrict__ WQ,
             const float* __restrict__ WK, float* __restrict__ out) {
    const uint32_t sb = smem_u32(dsm);
    const int tid  = threadIdx.x;
    const int lane = tid & 31;
    const int w    = tid >> 5;
    const int m0   = (w & 3) << 5;     // warp tile: 32m x 32n (grid 4m x 4n)
    const int n0   = (w >> 2) << 5;
    const int g    = lane >> 2;
    const int q    = lane & 3;
    const int bx   = blockIdx.x;

    // first tile prefetch ASAP (async; overlaps producer phase)
    issue_prefetch(In, bx, sb, 0, tid);

    // ---- producers: CTA c < NPROD computes column c of M -> B row + l1 partial ----
    if (bx < NPROD) {
        const int c = bx;
        float* sL1 = (float*)(dsm + RED);
        if (tid < 256) {
            const int i  = tid >> 1;      // M row index (k)
            const int jh = tid & 1;
            float acc = 0.f;
#pragma unroll 8
            for (int jj = 0; jj < 64; ++jj) {
                const int j = jh * 64 + jj;
                acc = fmaf(__ldg(WK + j * NDIM + i), __ldg(WQ + j * NDIM + c), acc);
            }
            acc += __shfl_xor_sync(0xffffffffu, acc, 1);
            if (jh == 0) {
                *(__nv_bfloat16*)((char*)g_Bsw + gsw(c, i)) = __float2bfloat16(acc);
                sL1[i] = 1.0f / (1.0f + __expf(-acc));      // sigmoid(M[i][c])
            }
        }
        __syncthreads();
        for (int o = 64; o; o >>= 1) {              // deterministic tree
            if (tid < o) sL1[tid] += sL1[tid + o];
            __syncthreads();
        }
        if (tid == 0) g_l1part[c] = sL1[0];
        __threadfence();
        __syncthreads();
        if (tid == 0) atomicAdd(&g_done, 1);
    }

    // ---- wait for all producers, stage B ----
    if (tid == 0) {
        int v;
        do {
            asm volatile("ld.acquire.gpu.b32 %0, [%1];" : "=r"(v) : "l"(&g_done) : "memory");
            if (v < NPROD) __nanosleep(64);
        } while (v < NPROD);
    }
    __syncthreads();
    {
        const float4* src = (const float4*)g_Bsw;
        float4* dst = (float4*)(dsm + BOF);
#pragma unroll
        for (int k = tid; k < 2048; k += 512) dst[k] = src[k];
    }

    const int rA0 = m0 + g;
    const uint32_t xA = (uint32_t)((g & 1) << 2);
    const uint32_t xB = (uint32_t)(g << 2);
    const uint32_t bB = sb + BOF + (uint32_t)(n0 + g) * 256;
    const uint32_t xN = (uint32_t)(((g + 1) & 1) << 2);   // row parity of rA+1 / rB+1

    const int nt = (NTILES - bx + NCTA - 1) / NCTA;
    float loss = 0.f;

    for (int i = 0; i < nt; ++i) {
        const int tile = bx + i * NCTA;
        const int slot = i & 1;
        const uint32_t stg = sb + (slot ? STG1 : STG0);
        const uint32_t bA = stg + (uint32_t)rA0 * 512;

        __syncthreads();                 // iter i-1 fully done with buf(1-slot); B staged (i=0)
        if (i + 1 < nt) {
            issue_prefetch(In, bx + (i + 1) * NCTA, sb, 1 - slot, tid);
            cpa_wait1();                 // fetch(i) landed (had all of iter i-1 to fly)
        } else {
            cpa_wait0();
        }
        __syncthreads();                 // buf(slot) visible to all

        // -------- mainloop --------
        float dacc[2][4][4];
#pragma unroll
        for (int mh = 0; mh < 2; ++mh)
#pragma unroll
            for (int nf = 0; nf < 4; ++nf)
#pragma unroll
                for (int j = 0; j < 4; ++j) dacc[mh][nf][j] = 0.f;
        float rsum[4] = {0.f, 0.f, 0.f, 0.f};

#pragma unroll
        for (int ks = 0; ks < 8; ++ks) {
            const uint32_t c = (uint32_t)(4 * ks + q);
            const uint32_t offA = ((c ^ xA) << 4);
            const float4 v00 = lds128f(bA + offA);               // row rA0
            const float4 v01 = lds128f(bA + 8 * 512 + offA);     // row rA0+8
            const float4 v10 = lds128f(bA + 16 * 512 + offA);    // row rA0+16
            const float4 v11 = lds128f(bA + 24 * 512 + offA);    // row rA0+24
            rsum[0] += (v00.x + v00.y) + (v00.z + v00.w);
            rsum[1] += (v01.x + v01.y) + (v01.z + v01.w);
            rsum[2] += (v10.x + v10.y) + (v10.z + v10.w);
            rsum[3] += (v11.x + v11.y) + (v11.z + v11.w);
            uint32_t a0[4], a1[4];
            a0[0] = bf2(v00.y, v00.x); a0[1] = bf2(v01.y, v01.x);
            a0[2] = bf2(v00.w, v00.z); a0[3] = bf2(v01.w, v01.z);
            a1[0] = bf2(v10.y, v10.x); a1[1] = bf2(v11.y, v11.x);
            a1[2] = bf2(v10.w, v10.z); a1[3] = bf2(v11.w, v11.z);
            const uint32_t offB = ((c ^ xB) << 3);
#pragma unroll
            for (int nf = 0; nf < 4; ++nf) {
                const uint2 b = lds64u(bB + (uint32_t)nf * 2048 + offB);
                mma_bf16(dacc[0][nf], a0, b.x, b.y);
                mma_bf16(dacc[1][nf], a1, b.x, b.y);
            }
        }

        // quad-reduce rowsums
#pragma unroll
        for (int j = 0; j < 4; ++j) {
            rsum[j] += __shfl_xor_sync(0xffffffffu, rsum[j], 1);
            rsum[j] += __shfl_xor_sync(0xffffffffu, rsum[j], 2);
        }

        // -------- epilogue (targets from this tile's staging; fp32 exact) --------
        const size_t base = (size_t)tile * TILE;
#pragma unroll
        for (int mh = 0; mh < 2; ++mh) {
            const int rA = m0 + 16 * mh + g;        // <= 119 (always valid)
            const int rB = rA + 8;                  // <= 127
            const float rsA = rsum[2 * mh];
            const float rsB = rsum[2 * mh + 1];
            const bool vB = (base + rB) < (size_t)(S_LEN - 1);
#pragma unroll
            for (int nf = 0; nf < 4; ++nf) {
                const int col0 = n0 + 8 * nf + 2 * q;
                const uint32_t off = (((uint32_t)(col0 >> 2) ^ xN) << 4) + ((col0 & 3) << 2);
                const float2 nxa = lds64f(stg + (uint32_t)(rA + 1) * 512 + off);
                const float2 nxb = (rB < TILE - 1)
                                       ? lds64f(stg + (uint32_t)(rB + 1) * 512 + off)
                                       : lds64f(sb + NXT + (uint32_t)slot * 512 + col0 * 4);
                const float* d = dacc[mh][nf];
                const float t0 = fmaf(softplusf(d[0]), rsA, -nxa.x);
                const float t1 = fmaf(softplusf(d[1]), rsA, -nxa.y);
                loss = fmaf(t0, t0, loss);
                loss = fmaf(t1, t1, loss);
                if (vB) {
                    const float t2 = fmaf(softplusf(d[2]), rsB, -nxb.x);
                    const float t3 = fmaf(softplusf(d[3]), rsB, -nxb.y);
                    loss = fmaf(t2, t2, loss);
                    loss = fmaf(t3, t3, loss);
                }
            }
        }
    }

    // ---- deterministic CTA reduction (512 threads) ----
    float* sRed = (float*)(dsm + RED);
    __syncthreads();
    sRed[tid] = loss;
    __syncthreads();
#pragma unroll
    for (int o = 256; o; o >>= 1) {
        if (tid < o) sRed[tid] += sRed[tid + o];
        __syncthreads();
    }
    if (tid == 0) g_partials[bx] = sRed[0];

    // ---- last-CTA final reduce (fixed-order => deterministic) ----
    __shared__ int sLast;
    if (tid == 0) {
        __threadfence();
        sLast = (atomicAdd(&g_ticket, 1) == NCTA - 1);
    }
    __syncthreads();
    if (sLast) {
        __threadfence();
        double* dRed = (double*)(dsm + RED);
        double s = (tid < NCTA) ? (double)__ldcg(&g_partials[tid]) : 0.0;
        dRed[tid] = s;
        __syncthreads();
        for (int o = 256; o; o >>= 1) {
            if (tid < o) dRed[tid] += dRed[tid + o];
            __syncthreads();
        }
        if (tid == 0)
            out[0] = (float)(dRed[0] / ((double)(S_LEN - 1) * (double)NDIM));
        __syncthreads();

        dRed[tid] = (tid < NPROD) ? (double)__ldcg(&g_l1part[tid]) : 0.0;
        __syncthreads();
        for (int o = 256; o; o >>= 1) {
            if (tid < o) dRed[tid] += dRed[tid + o];
            __syncthreads();
        }
        if (tid == 0) {
            out[1] = (float)dRed[0];
            g_done = 0;                  // reset for next graph replay
            g_ticket = 0;
        }
    }
}

// ---------------- launch ----------------
extern "C" void kernel_launch(void* const* d_in, const int* in_sizes, int n_in,
                              void* d_out, int out_size) {
    const float* In = (const float*)d_in[0];
    const float* WQ = (const float*)d_in[1];
    const float* WK = (const float*)d_in[2];
    float* out = (float*)d_out;

    cudaFuncSetAttribute(fused_kernel,
                         cudaFuncAttributeMaxDynamicSharedMemorySize, SMEM_BYTES);
    fused_kernel<<<NCTA, 512, SMEM_BYTES>>>(In, WQ, WK, out);
}

// round 15
// speedup vs baseline: 1.1244x; 1.1244x over previous
#include <cuda_runtime.h>
#include <cuda_bf16.h>
#include <cstdint>

#define S_LEN  262144
#define NDIM   128
#define TILE   128
#define NTILES 2048
#define NCTA   296        // 2 CTAs/SM x 148 SMs (all co-resident)
#define NPROD  128        // producer CTAs for W

// ---------------- device scratch ----------------
__device__ __align__(16) __nv_bfloat16 g_Bsw[NDIM * NDIM];  // B[t][k]=bf16(M[k][t]), swizzled
__device__ float g_partials[NCTA];
__device__ float g_l1part[NPROD];
__device__ int   g_done;       // producer counter (reset by last CTA)
__device__ int   g_ticket;     // completion ticket (reset by last CTA)

// ---------------- smem byte offsets (per CTA 100864 B -> 2 CTAs/SM) ----------------
#define STG   0          // fp32 staging: 128 x 512B = 65536 (single buffer)
#define BOF   65536      // B bf16 swizzled: 32768
#define NXT   98304      // boundary row fp32: 512
#define RED   98816      // reduction: 256 doubles = 2048 (aliases producer l1 floats)
#define SMEM_BYTES 100864

// ---------------- helpers ----------------
__device__ __forceinline__ uint32_t smem_u32(const void* p) {
    uint32_t a;
    asm("{ .reg .u64 t; cvta.to.shared.u64 t, %1; cvt.u32.u64 %0, t; }" : "=r"(a) : "l"(p));
    return a;
}
__device__ __forceinline__ uint32_t bf2(float xh, float xl) {
    uint32_t r;
    asm("cvt.rn.bf16x2.f32 %0, %1, %2;" : "=r"(r) : "f"(xh), "f"(xl));
    return r;
}
__device__ __forceinline__ float4 lds128f(uint32_t a) {
    float4 v;
    asm volatile("ld.shared.v4.f32 {%0,%1,%2,%3}, [%4];"
                 : "=f"(v.x), "=f"(v.y), "=f"(v.z), "=f"(v.w) : "r"(a));
    return v;
}
__device__ __forceinline__ float2 lds64f(uint32_t a) {
    float2 v;
    asm volatile("ld.shared.v2.f32 {%0,%1}, [%2];" : "=f"(v.x), "=f"(v.y) : "r"(a));
    return v;
}
__device__ __forceinline__ uint2 lds64u(uint32_t a) {
    uint2 v;
    asm volatile("ld.shared.v2.b32 {%0,%1}, [%2];" : "=r"(v.x), "=r"(v.y) : "r"(a));
    return v;
}
__device__ __forceinline__ void cpa16(uint32_t dst, const void* src) {
    asm volatile("cp.async.cg.shared.global [%0], [%1], 16;" :: "r"(dst), "l"(src));
}
__device__ __forceinline__ void cpa_commit() { asm volatile("cp.async.commit_group;" ::: "memory"); }
__device__ __forceinline__ void cpa_wait0()  { asm volatile("cp.async.wait_group 0;" ::: "memory"); }

__device__ __forceinline__ void mma_bf16(float* d, const uint32_t* a, uint32_t b0, uint32_t b1) {
    asm volatile(
        "mma.sync.aligned.m16n8k16.row.col.f32.bf16.bf16.f32 "
        "{%0,%1,%2,%3}, {%4,%5,%6,%7}, {%8,%9}, {%0,%1,%2,%3};"
        : "+f"(d[0]), "+f"(d[1]), "+f"(d[2]), "+f"(d[3])
        : "r"(a[0]), "r"(a[1]), "r"(a[2]), "r"(a[3]), "r"(b0), "r"(b1));
}
__device__ __forceinline__ float softplusf(float x) {
    const float l = __logf(1.0f + __expf(x));
    return (x > 15.0f) ? x : l;
}
// swizzled byte offset: B plane row t (256B rows), element index k
__device__ __forceinline__ uint32_t gsw(int t, int k) {
    return (uint32_t)(t * 256 + (((k >> 2) ^ ((t & 7) << 2)) << 3) + (k & 3) * 2);
}

// ---------------- fused persistent kernel ----------------
extern __shared__ char dsm[];

__device__ __forceinline__ void issue_prefetch(const float* __restrict__ In, int tile,
                                               uint32_t sb, int tid) {
    const char* src = (const char*)(In + (size_t)tile * TILE * NDIM);
#pragma unroll
    for (int j = 0; j < 16; ++j) {
        const int idx = tid + 256 * j;           // 4096 16B chunks
        const int r = idx >> 5, c = idx & 31;
        cpa16(sb + STG + r * 512 + ((c ^ ((r & 1) << 2)) << 4), src + r * 512 + c * 16);
    }
    if (tid < 32) {
        size_t nr = (size_t)tile * TILE + TILE;   // boundary row
        if (nr >= S_LEN) nr = 0;                   // clamped; masked in epilogue
        cpa16(sb + NXT + tid * 16, (const char*)(In + nr * NDIM) + tid * 16);
    }
    cpa_commit();
}

__global__ void __launch_bounds__(256, 2)
fused_kernel(const float* __restrict__ In, const float* __restrict__ WQ,
             const float* __restrict__ WK, float* __restrict__ out) {
    const uint32_t sb = smem_u32(dsm);
    const int tid  = threadIdx.x;
    const int lane = tid & 31;
    const int w    = tid >> 5;
    const int m0   = (w & 3) << 5;     // warp tile: 32m x 64n (grid 4m x 2n)
    const int n0   = (w >> 2) << 6;
    const int g    = lane >> 2;
    const int q    = lane & 3;
    const int bx   = blockIdx.x;

    // first tile prefetch ASAP (async; overlaps producer phase)
    issue_prefetch(In, bx, sb, tid);

    // ---- producers: CTA c < NPROD computes column c of M -> B row + l1 partial ----
    if (bx < NPROD) {
        const int c  = bx;
        const int i  = tid >> 1;      // M row index (k)
        const int jh = tid & 1;
        float acc = 0.f;
#pragma unroll 8
        for (int jj = 0; jj < 64; ++jj) {
            const int j = jh * 64 + jj;
            acc = fmaf(__ldg(WK + j * NDIM + i), __ldg(WQ + j * NDIM + c), acc);
        }
        acc += __shfl_xor_sync(0xffffffffu, acc, 1);
        float* sL1 = (float*)(dsm + RED);
        if (jh == 0) {
            *(__nv_bfloat16*)((char*)g_Bsw + gsw(c, i)) = __float2bfloat16(acc);
            sL1[i] = 1.0f / (1.0f + __expf(-acc));      // sigmoid(M[i][c])
        }
        __syncthreads();
        for (int o = 64; o; o >>= 1) {              // deterministic tree
            if (tid < o) sL1[tid] += sL1[tid + o];
            __syncthreads();
        }
        if (tid == 0) g_l1part[c] = sL1[0];
        __threadfence();
        __syncthreads();
        if (tid == 0) atomicAdd(&g_done, 1);
    }

    // ---- wait for all producers, stage B ----
    if (tid == 0) {
        int v;
        do {
            asm volatile("ld.acquire.gpu.b32 %0, [%1];" : "=r"(v) : "l"(&g_done) : "memory");
            if (v < NPROD) __nanosleep(64);
        } while (v < NPROD);
    }
    __syncthreads();
    {
        const float4* src = (const float4*)g_Bsw;
        float4* dst = (float4*)(dsm + BOF);
#pragma unroll
        for (int k = tid; k < 2048; k += 256) dst[k] = src[k];
    }

    const int rA0 = m0 + g;
    const uint32_t xA = (uint32_t)((g & 1) << 2);
    const uint32_t xB = (uint32_t)(g << 2);
    const uint32_t bA = sb + STG + (uint32_t)rA0 * 512;
    const uint32_t bB = sb + BOF + (uint32_t)(n0 + g) * 256;
    const uint32_t xN = (uint32_t)(((g + 1) & 1) << 2);   // row parity of rA+1 / rB+1

    const int nt = (NTILES - bx + NCTA - 1) / NCTA;
    float loss = 0.f;

    for (int i = 0; i < nt; ++i) {
        const int tile = bx + i * NCTA;
        cpa_wait0();
        __syncthreads();                 // staging + (first iter) B ready

        // -------- mainloop (R11-proven) --------
        float dacc[2][8][4];
#pragma unroll
        for (int mh = 0; mh < 2; ++mh)
#pragma unroll
            for (int nf = 0; nf < 8; ++nf)
#pragma unroll
                for (int j = 0; j < 4; ++j) dacc[mh][nf][j] = 0.f;
        float rsum[4] = {0.f, 0.f, 0.f, 0.f};

#pragma unroll
        for (int ks = 0; ks < 8; ++ks) {
            const uint32_t c = (uint32_t)(4 * ks + q);
            const uint32_t offA = ((c ^ xA) << 4);
            const float4 v00 = lds128f(bA + offA);               // row rA0
            const float4 v01 = lds128f(bA + 8 * 512 + offA);     // row rA0+8
            const float4 v10 = lds128f(bA + 16 * 512 + offA);    // row rA0+16
            const float4 v11 = lds128f(bA + 24 * 512 + offA);    // row rA0+24
            rsum[0] += (v00.x + v00.y) + (v00.z + v00.w);
            rsum[1] += (v01.x + v01.y) + (v01.z + v01.w);
            rsum[2] += (v10.x + v10.y) + (v10.z + v10.w);
            rsum[3] += (v11.x + v11.y) + (v11.z + v11.w);
            uint32_t a0[4], a1[4];
            a0[0] = bf2(v00.y, v00.x); a0[1] = bf2(v01.y, v01.x);
            a0[2] = bf2(v00.w, v00.z); a0[3] = bf2(v01.w, v01.z);
            a1[0] = bf2(v10.y, v10.x); a1[1] = bf2(v11.y, v11.x);
            a1[2] = bf2(v10.w, v10.z); a1[3] = bf2(v11.w, v11.z);
            const uint32_t offB = ((c ^ xB) << 3);
#pragma unroll
            for (int nf = 0; nf < 8; ++nf) {
                const uint2 b = lds64u(bB + (uint32_t)nf * 2048 + offB);
                mma_bf16(dacc[0][nf], a0, b.x, b.y);
                mma_bf16(dacc[1][nf], a1, b.x, b.y);
            }
        }

        // -------- softplus burst IN PLACE (independent of shuffles/LDS below) --------
#pragma unroll
        for (int mh = 0; mh < 2; ++mh)
#pragma unroll
            for (int nf = 0; nf < 8; ++nf)
#pragma unroll
                for (int j = 0; j < 4; ++j)
                    dacc[mh][nf][j] = softplusf(dacc[mh][nf][j]);

        // quad-reduce rowsums (overlaps the MUFU burst above in the pipeline)
#pragma unroll
        for (int j = 0; j < 4; ++j) {
            rsum[j] += __shfl_xor_sync(0xffffffffu, rsum[j], 1);
            rsum[j] += __shfl_xor_sync(0xffffffffu, rsum[j], 2);
        }

        // -------- epilogue: fast path (no boundary checks) for all tiles but the last --------
        if (tile != NTILES - 1) {
#pragma unroll
            for (int mh = 0; mh < 2; ++mh) {
                const int rA = m0 + 16 * mh + g;        // <= 119
                const int rB = rA + 8;                  // <= 127
                const float rsA = rsum[2 * mh];
                const float rsB = rsum[2 * mh + 1];
#pragma unroll
                for (int nf = 0; nf < 8; ++nf) {
                    const int col0 = n0 + 8 * nf + 2 * q;
                    const uint32_t off = (((uint32_t)(col0 >> 2) ^ xN) << 4) + ((col0 & 3) << 2);
                    const float2 nxa = lds64f(sb + STG + (uint32_t)(rA + 1) * 512 + off);
                    const float2 nxb = (rB < TILE - 1)
                                           ? lds64f(sb + STG + (uint32_t)(rB + 1) * 512 + off)
                                           : lds64f(sb + NXT + col0 * 4);
                    const float* d = dacc[mh][nf];
                    const float t0 = fmaf(d[0], rsA, -nxa.x);
                    const float t1 = fmaf(d[1], rsA, -nxa.y);
                    const float t2 = fmaf(d[2], rsB, -nxb.x);
                    const float t3 = fmaf(d[3], rsB, -nxb.y);
                    loss = fmaf(t0, t0, loss);
                    loss = fmaf(t1, t1, loss);
                    loss = fmaf(t2, t2, loss);
                    loss = fmaf(t3, t3, loss);
                }
            }
        } else {
            // slow path: one CTA, one iteration (tile 2047)
            const size_t base = (size_t)tile * TILE;
#pragma unroll
            for (int mh = 0; mh < 2; ++mh) {
                const int rA = m0 + 16 * mh + g;
                const int rB = rA + 8;
                const float rsA = rsum[2 * mh];
                const float rsB = rsum[2 * mh + 1];
                const bool vB = (base + rB) < (size_t)(S_LEN - 1);
#pragma unroll
                for (int nf = 0; nf < 8; ++nf) {
                    const int col0 = n0 + 8 * nf + 2 * q;
                    const uint32_t off = (((uint32_t)(col0 >> 2) ^ xN) << 4) + ((col0 & 3) << 2);
                    const float2 nxa = lds64f(sb + STG + (uint32_t)(rA + 1) * 512 + off);
                    const float2 nxb = (rB < TILE - 1)
                                           ? lds64f(sb + STG + (uint32_t)(rB + 1) * 512 + off)
                                           : lds64f(sb + NXT + col0 * 4);
                    const float* d = dacc[mh][nf];
                    const float t0 = fmaf(d[0], rsA, -nxa.x);
                    const float t1 = fmaf(d[1], rsA, -nxa.y);
                    loss = fmaf(t0, t0, loss);
                    loss = fmaf(t1, t1, loss);
                    if (vB) {
                        const float t2 = fmaf(d[2], rsB, -nxb.x);
                        const float t3 = fmaf(d[3], rsB, -nxb.y);
                        loss = fmaf(t2, t2, loss);
                        loss = fmaf(t3, t3, loss);
                    }
                }
            }
        }

        __syncthreads();                 // all warps done reading staging + NXT
        if (i + 1 < nt) issue_prefetch(In, bx + (i + 1) * NCTA, sb, tid);
    }

    // ---- deterministic CTA reduction ----
    float* sRed = (float*)(dsm + RED);
    sRed[tid] = loss;
    __syncthreads();
#pragma unroll
    for (int o = 128; o; o >>= 1) {
        if (tid < o) sRed[tid] += sRed[tid + o];
        __syncthreads();
    }
    if (tid == 0) g_partials[bx] = sRed[0];

    // ---- last-CTA final reduce (fixed-order => deterministic) ----
    __shared__ int sLast;
    if (tid == 0) {
        __threadfence();
        sLast = (atomicAdd(&g_ticket, 1) == NCTA - 1);
    }
    __syncthreads();
    if (sLast) {
        __threadfence();
        double* dRed = (double*)(dsm + RED);
        double s = 0.0;
        for (int k = tid; k < NCTA; k += 256) s += (double)__ldcg(&g_partials[k]);
        dRed[tid] = s;
        __syncthreads();
        for (int o = 128; o; o >>= 1) {
            if (tid < o) dRed[tid] += dRed[tid + o];
            __syncthreads();
        }
        if (tid == 0)
            out[0] = (float)(dRed[0] / ((double)(S_LEN - 1) * (double)NDIM));
        __syncthreads();

        dRed[tid] = (tid < NPROD) ? (double)__ldcg(&g_l1part[tid]) : 0.0;
        __syncthreads();
        for (int o = 128; o; o >>= 1) {
            if (tid < o) dRed[tid] += dRed[tid + o];
            __syncthreads();
        }
        if (tid == 0) {
            out[1] = (float)dRed[0];
            g_done = 0;                  // reset for next graph replay
            g_ticket = 0;
        }
    }
}

// ---------------- launch ----------------
extern "C" void kernel_launch(void* const* d_in, const int* in_sizes, int n_in,
                              void* d_out, int out_size) {
    const float* In = (const float*)d_in[0];
    const float* WQ = (const float*)d_in[1];
    const float* WK = (const float*)d_in[2];
    float* out = (float*)d_out;

    cudaFuncSetAttribute(fused_kernel,
                         cudaFuncAttributeMaxDynamicSharedMemorySize, SMEM_BYTES);
    fused_kernel<<<NCTA, 256, SMEM_BYTES>>>(In, WQ, WK, out);
}